// round 1
// baseline (speedup 1.0000x reference)
#include <cuda_runtime.h>
#include <cuda_bf16.h>

// ---------------------------------------------------------------------------
// SS2D (VMamba 2D selective scan)
// B=4, H=W=56, L=3136, d_model=96, d_inner=192, dstate=16, K=4 dirs, rank=6
//
// Pipeline:
//  1. gemm<0>   : xz = x @ in_proj_w^T            [12544 x 384]
//  2. split_silu: xz -> xc_raw [12544x192], z=silu [12544x192]
//  3. conv_dw   : depthwise 3x3 + bias + silu -> xc [12544x192]
//  4. gemm<1>   : per-direction x_dbl proj (dt|B|C) -> proj [B,K,L,40] (padded)
//  5. dt_kernel : delta = softplus(dt @ dt_w + bias) [B,K,L,192]
//  6. phase1    : per-chunk (112 steps) local scan: prodA + local h_end
//  7. phase2    : 28-step scan over chunks per (b,k,d,n) channel
//  8. phase3    : re-run chunks with true entry state, emit y + Ds*u at
//                 direction-mapped spatial position -> yout [B,K,L,192]
//  9. merge_ln  : sum 4 dirs, LayerNorm over 192, gate with z -> gated
// 10. gemm<2>   : out = gated @ out_proj_w^T      [12544 x 96]
// ---------------------------------------------------------------------------

#define L_LEN   3136
#define D_IN    192
#define N_ST    16
#define M_ROWS  12544        // B*L
#define NCHUNK  28
#define CLEN    112

// ---------------- scratch (static device globals; no allocation) -----------
__device__ __align__(256) float g_xz    [M_ROWS * 384];
__device__ __align__(256) float g_xcraw [M_ROWS * D_IN];
__device__ __align__(256) float g_xc    [M_ROWS * D_IN];
__device__ __align__(256) float g_z     [M_ROWS * D_IN];
__device__ __align__(256) float g_proj  [4 * 4 * L_LEN * 40];
__device__ __align__(256) float g_delta [4 * 4 * L_LEN * D_IN];
__device__ __align__(256) float g_cA    [4 * 4 * NCHUNK * D_IN * N_ST];
__device__ __align__(256) float g_cH    [4 * 4 * NCHUNK * D_IN * N_ST];
__device__ __align__(256) float g_hs    [4 * 4 * NCHUNK * D_IN * N_ST];
__device__ __align__(256) float g_yout  [4 * 4 * L_LEN * D_IN];
__device__ __align__(256) float g_gated [M_ROWS * D_IN];

// direction k scan-index l -> spatial position (h*56+w)
__device__ __forceinline__ int dir_pos(int k, int l) {
    int l2 = (k >= 2) ? (L_LEN - 1 - l) : l;
    if (k & 1) {                       // WH order: l2 = w*56 + h
        int h = l2 % 56, w = l2 / 56;
        return h * 56 + w;
    }
    return l2;                         // HW order
}

// ---------------------------------------------------------------------------
// GEMM: C = A @ W^T.  A [M x Kd] row-major, W [N x Kd] row-major.
// SEL=0: A = param x,      C = g_xz  (N=384, Kd=96)
// SEL=1: A = g_xc (rows permuted per direction k = blockIdx.z),
//        W += k*38*Kd, C rows -> proj[B,K,L,40] with col 0..5 -> 0..5,
//        col 6..37 -> 8..39 (B at +8, C at +24, float4 aligned)
// SEL=2: A = g_gated,      C = param out (N=96, Kd=192)
// Tile 64x64, BK=16, 256 threads, 4x4 micro-tile / thread.
// ---------------------------------------------------------------------------
template<int SEL>
__global__ void __launch_bounds__(256)
gemm_tn(const float* __restrict__ Aopt, const float* __restrict__ Wg,
        float* __restrict__ Copt, int N, int Kd)
{
    __shared__ float As[16][68];
    __shared__ float Ws[16][68];

    const float* A;
    if      (SEL == 0) A = Aopt;
    else if (SEL == 1) A = g_xc;
    else               A = g_gated;

    int kdir = (SEL == 1) ? (int)blockIdx.z : 0;
    const float* W = (SEL == 1) ? (Wg + kdir * 38 * Kd) : Wg;

    int t  = threadIdx.x;
    int bm = blockIdx.x, bn = blockIdx.y;

    // load-phase indices (fixed across K loop)
    int lm  = t >> 2;            // 0..63
    int kq  = (t & 3) * 4;       // 0,4,8,12
    int m_g = bm * 64 + lm;      // < 12544 always
    int aRow;
    if (SEL == 1) {
        int b = m_g / L_LEN, l = m_g - b * L_LEN;
        aRow = b * L_LEN + dir_pos(kdir, l);
    } else {
        aRow = m_g;
    }
    int n_g  = bn * 64 + lm;
    bool wok = (n_g < N);

    int ty = t >> 4, tx = t & 15;
    float acc[4][4];
    #pragma unroll
    for (int i = 0; i < 4; i++)
        #pragma unroll
        for (int j = 0; j < 4; j++) acc[i][j] = 0.f;

    for (int k0 = 0; k0 < Kd; k0 += 16) {
        float4 av = *(const float4*)&A[aRow * Kd + k0 + kq];
        float4 wv = make_float4(0.f, 0.f, 0.f, 0.f);
        if (wok) wv = *(const float4*)&W[n_g * Kd + k0 + kq];
        __syncthreads();
        As[kq + 0][lm] = av.x; As[kq + 1][lm] = av.y;
        As[kq + 2][lm] = av.z; As[kq + 3][lm] = av.w;
        Ws[kq + 0][lm] = wv.x; Ws[kq + 1][lm] = wv.y;
        Ws[kq + 2][lm] = wv.z; Ws[kq + 3][lm] = wv.w;
        __syncthreads();
        #pragma unroll
        for (int kk = 0; kk < 16; kk++) {
            float a0 = As[kk][ty],      a1 = As[kk][ty + 16];
            float a2 = As[kk][ty + 32], a3 = As[kk][ty + 48];
            float b0 = Ws[kk][tx],      b1 = Ws[kk][tx + 16];
            float b2 = Ws[kk][tx + 32], b3 = Ws[kk][tx + 48];
            acc[0][0] = fmaf(a0, b0, acc[0][0]); acc[0][1] = fmaf(a0, b1, acc[0][1]);
            acc[0][2] = fmaf(a0, b2, acc[0][2]); acc[0][3] = fmaf(a0, b3, acc[0][3]);
            acc[1][0] = fmaf(a1, b0, acc[1][0]); acc[1][1] = fmaf(a1, b1, acc[1][1]);
            acc[1][2] = fmaf(a1, b2, acc[1][2]); acc[1][3] = fmaf(a1, b3, acc[1][3]);
            acc[2][0] = fmaf(a2, b0, acc[2][0]); acc[2][1] = fmaf(a2, b1, acc[2][1]);
            acc[2][2] = fmaf(a2, b2, acc[2][2]); acc[2][3] = fmaf(a2, b3, acc[2][3]);
            acc[3][0] = fmaf(a3, b0, acc[3][0]); acc[3][1] = fmaf(a3, b1, acc[3][1]);
            acc[3][2] = fmaf(a3, b2, acc[3][2]); acc[3][3] = fmaf(a3, b3, acc[3][3]);
        }
    }

    #pragma unroll
    for (int i = 0; i < 4; i++) {
        int gr = bm * 64 + ty + 16 * i;
        #pragma unroll
        for (int j = 0; j < 4; j++) {
            int gc = bn * 64 + tx + 16 * j;
            if (gc < N) {
                if (SEL == 1) {
                    int b = gr / L_LEN, l = gr - b * L_LEN;
                    int crow = (b * 4 + kdir) * L_LEN + l;
                    int cc   = (gc < 6) ? gc : gc + 2;
                    g_proj[crow * 40 + cc] = acc[i][j];
                } else if (SEL == 0) {
                    g_xz[gr * 384 + gc] = acc[i][j];
                } else {
                    Copt[gr * 96 + gc] = acc[i][j];
                }
            }
        }
    }
}

// ---------------------------------------------------------------------------
__global__ void __launch_bounds__(256) split_silu_kernel()
{
    int idx = blockIdx.x * 256 + threadIdx.x;      // < 12544*384
    int m = idx / 384, j = idx - m * 384;
    float v = g_xz[idx];
    if (j < D_IN) {
        g_xcraw[m * D_IN + j] = v;
    } else {
        g_z[m * D_IN + (j - D_IN)] = v / (1.f + __expf(-v));
    }
}

__global__ void __launch_bounds__(256)
conv_dw_kernel(const float* __restrict__ cw, const float* __restrict__ cb)
{
    int idx = blockIdx.x * 256 + threadIdx.x;      // < 12544*192
    int d = idx % D_IN;
    int m = idx / D_IN;
    int pos = m % L_LEN;
    int b   = m / L_LEN;
    int h = pos / 56, w = pos % 56;
    float acc = cb[d];
    #pragma unroll
    for (int kh = 0; kh < 3; kh++) {
        int hh = h + kh - 1;
        if (hh < 0 || hh >= 56) continue;
        #pragma unroll
        for (int kw = 0; kw < 3; kw++) {
            int ww = w + kw - 1;
            if (ww < 0 || ww >= 56) continue;
            acc = fmaf(g_xcraw[(b * L_LEN + hh * 56 + ww) * D_IN + d],
                       cw[d * 9 + kh * 3 + kw], acc);
        }
    }
    g_xc[idx] = acc / (1.f + __expf(-acc));        // SiLU
}

__global__ void __launch_bounds__(256)
dt_kernel(const float* __restrict__ dtw, const float* __restrict__ dtb)
{
    int idx = blockIdx.x * 256 + threadIdx.x;      // < 4*4*3136*192
    int d  = idx % D_IN;
    int l  = (idx / D_IN) % L_LEN;
    int bk = idx / (D_IN * L_LEN);                 // b*4+k
    int k  = bk & 3;
    const float* pr = &g_proj[(bk * L_LEN + l) * 40];
    float s = dtb[k * D_IN + d];
    const float* wr = &dtw[(k * D_IN + d) * 6];
    #pragma unroll
    for (int r = 0; r < 6; r++) s = fmaf(wr[r], pr[r], s);
    // numerically stable softplus
    g_delta[idx] = fmaxf(s, 0.f) + log1pf(__expf(-fabsf(s)));
}

// ---------------------------------------------------------------------------
// Phase 1: per (b,k,chunk), thread = d. h starts at 0; track prod(dA) and h.
// ---------------------------------------------------------------------------
__global__ void __launch_bounds__(192)
scan_phase1(const float* __restrict__ A_logs)
{
    int bid = blockIdx.x;                 // 448 = B*K*NCHUNK
    int c = bid % NCHUNK;
    int k = (bid / NCHUNK) & 3;
    int b = bid / (NCHUNK * 4);
    int d = threadIdx.x;
    int bk = b * 4 + k;

    float Ar[N_ST], h[N_ST], ap[N_ST];
    #pragma unroll
    for (int n = 0; n < N_ST; n++) {
        Ar[n] = -__expf(A_logs[(k * D_IN + d) * N_ST + n]);
        h[n] = 0.f; ap[n] = 1.f;
    }

    int l0 = c * CLEN;
    for (int t = 0; t < CLEN; t++) {
        int l = l0 + t;
        float dt = g_delta[(bk * L_LEN + l) * D_IN + d];
        int pos = dir_pos(k, l);
        float u = g_xc[(b * L_LEN + pos) * D_IN + d];
        const float4* p = (const float4*)&g_proj[(bk * L_LEN + l) * 40 + 8];
        float4 q0 = p[0], q1 = p[1], q2 = p[2], q3 = p[3];
        float Bv[N_ST] = {q0.x,q0.y,q0.z,q0.w, q1.x,q1.y,q1.z,q1.w,
                          q2.x,q2.y,q2.z,q2.w, q3.x,q3.y,q3.z,q3.w};
        float dtu = dt * u;
        #pragma unroll
        for (int n = 0; n < N_ST; n++) {
            float dA = __expf(dt * Ar[n]);
            ap[n] *= dA;
            h[n] = fmaf(dA, h[n], Bv[n] * dtu);
        }
    }
    int ob = (bk * NCHUNK + c) * (D_IN * N_ST) + d * N_ST;
    #pragma unroll
    for (int n = 0; n < N_ST; n += 4) {
        *(float4*)&g_cA[ob + n] = make_float4(ap[n], ap[n+1], ap[n+2], ap[n+3]);
        *(float4*)&g_cH[ob + n] = make_float4(h[n],  h[n+1],  h[n+2],  h[n+3]);
    }
}

// Phase 2: scan across chunks per (b,k,d,n) channel. Stores entry state/chunk.
__global__ void __launch_bounds__(256) scan_phase2()
{
    int tid = blockIdx.x * 256 + threadIdx.x;      // < 16*3072
    int bk = tid / (D_IN * N_ST);
    int r  = tid % (D_IN * N_ST);
    float h = 0.f;
    #pragma unroll 4
    for (int c = 0; c < NCHUNK; c++) {
        int idx = (bk * NCHUNK + c) * (D_IN * N_ST) + r;
        g_hs[idx] = h;
        h = fmaf(g_cA[idx], h, g_cH[idx]);
    }
}

// Phase 3: re-run chunk with true entry state; emit y + Ds*u to spatial pos.
__global__ void __launch_bounds__(192)
scan_phase3(const float* __restrict__ A_logs, const float* __restrict__ Ds)
{
    int bid = blockIdx.x;
    int c = bid % NCHUNK;
    int k = (bid / NCHUNK) & 3;
    int b = bid / (NCHUNK * 4);
    int d = threadIdx.x;
    int bk = b * 4 + k;

    float Ar[N_ST], h[N_ST];
    #pragma unroll
    for (int n = 0; n < N_ST; n++)
        Ar[n] = -__expf(A_logs[(k * D_IN + d) * N_ST + n]);
    int hb = (bk * NCHUNK + c) * (D_IN * N_ST) + d * N_ST;
    #pragma unroll
    for (int n = 0; n < N_ST; n += 4) {
        float4 v = *(const float4*)&g_hs[hb + n];
        h[n] = v.x; h[n+1] = v.y; h[n+2] = v.z; h[n+3] = v.w;
    }
    float Dv = Ds[k * D_IN + d];

    int l0 = c * CLEN;
    for (int t = 0; t < CLEN; t++) {
        int l = l0 + t;
        float dt = g_delta[(bk * L_LEN + l) * D_IN + d];
        int pos = dir_pos(k, l);
        float u = g_xc[(b * L_LEN + pos) * D_IN + d];
        const float4* p = (const float4*)&g_proj[(bk * L_LEN + l) * 40 + 8];
        float4 q0 = p[0], q1 = p[1], q2 = p[2], q3 = p[3];
        float4 r0 = p[4], r1 = p[5], r2 = p[6], r3 = p[7];
        float Bv[N_ST] = {q0.x,q0.y,q0.z,q0.w, q1.x,q1.y,q1.z,q1.w,
                          q2.x,q2.y,q2.z,q2.w, q3.x,q3.y,q3.z,q3.w};
        float Cv[N_ST] = {r0.x,r0.y,r0.z,r0.w, r1.x,r1.y,r1.z,r1.w,
                          r2.x,r2.y,r2.z,r2.w, r3.x,r3.y,r3.z,r3.w};
        float dtu = dt * u;
        float y0 = 0.f, y1 = 0.f;
        #pragma unroll
        for (int n = 0; n < N_ST; n += 2) {
            float dA0 = __expf(dt * Ar[n]);
            h[n] = fmaf(dA0, h[n], Bv[n] * dtu);
            y0 = fmaf(h[n], Cv[n], y0);
            float dA1 = __expf(dt * Ar[n + 1]);
            h[n+1] = fmaf(dA1, h[n+1], Bv[n+1] * dtu);
            y1 = fmaf(h[n+1], Cv[n+1], y1);
        }
        g_yout[(bk * L_LEN + pos) * D_IN + d] = y0 + y1 + Dv * u;
    }
}

// ---------------------------------------------------------------------------
// Merge 4 directions + LayerNorm(192) + gate with z
// ---------------------------------------------------------------------------
__global__ void __launch_bounds__(192)
merge_ln_kernel(const float* __restrict__ gamma, const float* __restrict__ beta)
{
    int m = blockIdx.x;                  // b*L + pos
    int b = m / L_LEN;
    int pos = m - b * L_LEN;
    int d = threadIdx.x;

    float y = 0.f;
    #pragma unroll
    for (int k = 0; k < 4; k++)
        y += g_yout[((b * 4 + k) * L_LEN + pos) * D_IN + d];

    float s = y, s2 = y * y;
    #pragma unroll
    for (int o = 16; o > 0; o >>= 1) {
        s  += __shfl_xor_sync(0xffffffffu, s,  o);
        s2 += __shfl_xor_sync(0xffffffffu, s2, o);
    }
    __shared__ float sh[16];
    int w = d >> 5, ln = d & 31;
    if (ln == 0) { sh[w] = s; sh[8 + w] = s2; }
    __syncthreads();
    if (d == 0) {
        float S = 0.f, S2 = 0.f;
        #pragma unroll
        for (int i = 0; i < 6; i++) { S += sh[i]; S2 += sh[8 + i]; }
        sh[0] = S; sh[8] = S2;
    }
    __syncthreads();
    float mu  = sh[0] * (1.f / 192.f);
    float var = sh[8] * (1.f / 192.f) - mu * mu;
    float rs  = rsqrtf(var + 1e-5f);
    float g = fmaf((y - mu) * rs, gamma[d], beta[d]) * g_z[m * D_IN + d];
    g_gated[m * D_IN + d] = g;
}

// ---------------------------------------------------------------------------
extern "C" void kernel_launch(void* const* d_in, const int* in_sizes, int n_in,
                              void* d_out, int out_size)
{
    const float* x      = (const float*)d_in[0];
    const float* in_w   = (const float*)d_in[1];
    const float* conv_w = (const float*)d_in[2];
    const float* conv_b = (const float*)d_in[3];
    const float* xpw    = (const float*)d_in[4];
    const float* dtw    = (const float*)d_in[5];
    const float* dtb    = (const float*)d_in[6];
    const float* A_logs = (const float*)d_in[7];
    const float* Ds     = (const float*)d_in[8];
    const float* gamma  = (const float*)d_in[9];
    const float* beta   = (const float*)d_in[10];
    const float* out_w  = (const float*)d_in[11];
    float* out = (float*)d_out;

    gemm_tn<0><<<dim3(M_ROWS / 64, 6, 1), 256>>>(x, in_w, nullptr, 384, 96);
    split_silu_kernel<<<(M_ROWS * 384) / 256, 256>>>();
    conv_dw_kernel<<<(M_ROWS * D_IN) / 256, 256>>>(conv_w, conv_b);
    gemm_tn<1><<<dim3(M_ROWS / 64, 1, 4), 256>>>(nullptr, xpw, nullptr, 38, 192);
    dt_kernel<<<(4 * 4 * L_LEN * D_IN) / 256, 256>>>(dtw, dtb);
    scan_phase1<<<4 * 4 * NCHUNK, 192>>>(A_logs);
    scan_phase2<<<(16 * D_IN * N_ST) / 256, 256>>>();
    scan_phase3<<<4 * 4 * NCHUNK, 192>>>(A_logs, Ds);
    merge_ln_kernel<<<M_ROWS, 192>>>(gamma, beta);
    gemm_tn<2><<<dim3(M_ROWS / 64, 2, 1), 256>>>(nullptr, out_w, out, 96, 192);
}